// round 2
// baseline (speedup 1.0000x reference)
#include <cuda_runtime.h>
#include <cstdint>
#include <cstddef>

#define B_ 4096
#define T_ 168
#define D_ 64
#define H_ 128
#define G_ 384   // 3*H

typedef unsigned long long ull;

// ---------------------------------------------------------------------------
// Packed fp32x2 helpers (Blackwell): one FFMA2 = 2 fp32 FMAs per issue slot,
// recovering full fp32 rate vs rt=2 FFMA-3reg. K accumulated pairwise
// (even k in .lo, odd k in .hi), horizontal lo+hi at the end (reassociation
// only; bit-harmless for this tolerance).
// ---------------------------------------------------------------------------
__device__ __forceinline__ ull ffma2(ull a, ull b, ull c) {
    ull d;
    asm("fma.rn.f32x2 %0, %1, %2, %3;" : "=l"(d) : "l"(a), "l"(b), "l"(c));
    return d;
}
__device__ __forceinline__ float f2sum(ull v) {
    float lo = __uint_as_float((unsigned)(v & 0xffffffffull));
    float hi = __uint_as_float((unsigned)(v >> 32));
    return lo + hi;
}

__device__ __forceinline__ float fast_sigmoid(float x) {
    return __fdividef(1.f, 1.f + __expf(-x));     // 2 MUFU
}
__device__ __forceinline__ float fast_tanh(float x) {
    return __fdividef(2.f, 1.f + __expf(-2.f * x)) - 1.f;   // 2 MUFU
}

__device__ __forceinline__ void cpasync16(void* smem_dst, const void* gsrc) {
    unsigned saddr = (unsigned)__cvta_generic_to_shared(smem_dst);
    asm volatile("cp.async.ca.shared.global [%0], [%1], 16;\n" :: "r"(saddr), "l"(gsrc));
}
#define CP_COMMIT() asm volatile("cp.async.commit_group;\n" ::: "memory")
#define CP_WAIT(n)  asm volatile("cp.async.wait_group %0;\n" :: "n"(n) : "memory")

// Scratch: gx[t][b][g] (fp32), ~1.01 GB device global (no cudaMalloc allowed).
__device__ float g_gx[(size_t)T_ * B_ * G_];

// ---------------------------------------------------------------------------
// Kernel A: gx[t][b][g] = feats[b][t][:] . W_ih[g][:D] + b_ih[g]
// Persistent: 148 blocks = 4 gate-slices (96 gates) x 37 m-tile walkers.
// Each block loads its W slice once; feats tiles double-buffered via cp.async.
// Micro-kernel: 256 thr, thread tile 4 rows x 12 gates, f32x2 K-pair accum.
// ---------------------------------------------------------------------------
#define A_NT   96
#define A_MT   128
#define A_PAD  68    // floats per smem row (16B aligned, bank-spread)

__global__ void __launch_bounds__(256, 1)
gx_kernel(const float* __restrict__ feats, const float* __restrict__ W_ih,
          const float* __restrict__ b_ih)
{
    extern __shared__ float smemA[];
    float* sW  = smemA;                       // 96*68
    float* sF0 = sW + A_NT * A_PAD;           // 128*68
    float* sF1 = sF0 + A_MT * A_PAD;          // 128*68
    float* sB  = sF1 + A_MT * A_PAD;          // 96

    const int tid  = threadIdx.x;
    const int wid  = tid >> 5;
    const int lane = tid & 31;
    const int slice = blockIdx.x & 3;         // gate slice 0..3
    const int px    = blockIdx.x >> 2;        // 0..36
    const int g_base = slice * A_NT;

    for (int i = tid; i < A_NT * D_; i += 256) {
        int g = i >> 6, d = i & 63;
        sW[g * A_PAD + d] = W_ih[(size_t)(g_base + g) * (D_ + 1) + d];
    }
    for (int i = tid; i < A_NT; i += 256) sB[i] = b_ih[g_base + i];

    const int NTILES = (B_ * T_) / A_MT;      // 5376
    float* sF[2] = { sF0, sF1 };

    // prefetch first tile: 128 rows * 64 floats = 2048 x 16B chunks, 8/thread
    {
        size_t base = (size_t)px * A_MT * D_;
        for (int i = 0; i < 8; i++) {
            int ci = tid + i * 256;
            int row = ci >> 4, seg = ci & 15;
            cpasync16(sF0 + row * A_PAD + seg * 4, feats + base + (size_t)ci * 4);
        }
        CP_COMMIT();
    }

    int buf = 0;
    for (int mt = px; mt < NTILES; mt += 37) {
        int mt_next = mt + 37;
        if (mt_next < NTILES) {
            size_t base = (size_t)mt_next * A_MT * D_;
            float* dst = sF[buf ^ 1];
            for (int i = 0; i < 8; i++) {
                int ci = tid + i * 256;
                int row = ci >> 4, seg = ci & 15;
                cpasync16(dst + row * A_PAD + seg * 4, feats + base + (size_t)ci * 4);
            }
            CP_COMMIT();
            CP_WAIT(1);
        } else {
            CP_WAIT(0);
        }
        __syncthreads();

        const ulonglong2* sF16 = reinterpret_cast<const ulonglong2*>(sF[buf]);
        const ulonglong2* sW16 = reinterpret_cast<const ulonglong2*>(sW);

        ull acc[4][12];
        #pragma unroll
        for (int a = 0; a < 4; a++)
            #pragma unroll
            for (int u = 0; u < 12; u++) acc[a][u] = 0ull;

        #pragma unroll 4
        for (int k4 = 0; k4 < 16; k4++) {           // K=64 as 16 x float4
            ulonglong2 f[4];
            #pragma unroll
            for (int rr = 0; rr < 4; rr++) {
                int row = lane + rr * 32;           // 2-way-max bank spread
                f[rr] = sF16[row * 17 + k4];        // 68 floats = 17 x 16B
            }
            #pragma unroll
            for (int u = 0; u < 12; u++) {
                int g = wid * 12 + u;               // warp-broadcast W loads
                ulonglong2 w = sW16[g * 17 + k4];
                #pragma unroll
                for (int rr = 0; rr < 4; rr++) {
                    acc[rr][u] = ffma2(f[rr].x, w.x, acc[rr][u]);
                    acc[rr][u] = ffma2(f[rr].y, w.y, acc[rr][u]);
                }
            }
        }

        // store: gx layout [T][B][G]
        #pragma unroll
        for (int rr = 0; rr < 4; rr++) {
            int m = mt * A_MT + lane + rr * 32;     // m = b*T + t
            int b = m / T_;
            int t = m - b * T_;
            size_t obase = ((size_t)t * B_ + b) * G_ + g_base + wid * 12;
            #pragma unroll
            for (int v = 0; v < 3; v++) {
                float4 o;
                o.x = f2sum(acc[rr][v * 4 + 0]) + sB[wid * 12 + v * 4 + 0];
                o.y = f2sum(acc[rr][v * 4 + 1]) + sB[wid * 12 + v * 4 + 1];
                o.z = f2sum(acc[rr][v * 4 + 2]) + sB[wid * 12 + v * 4 + 2];
                o.w = f2sum(acc[rr][v * 4 + 3]) + sB[wid * 12 + v * 4 + 3];
                *reinterpret_cast<float4*>(&g_gx[obase + v * 4]) = o;
            }
        }
        __syncthreads();   // protect sF[buf] before next prefetch overwrites
        buf ^= 1;
    }
}

// ---------------------------------------------------------------------------
// Kernel B: persistent GRU scan. 128 blocks x 256 threads, 32 batch rows each.
// W_hh (384x128 fp32, pad 130) resident in smem for all 168 steps.
// Thread tile: 4 rows x 4 h-channels x {r,z,n}: 48 f32x2 accumulators.
// Lane map lane = rg*4 + jg: conflict-light h loads (8 addr, 4-way bcast)
// and W loads (4 addr, 8-way bcast).
// gx LDGs are issued at loop top, consumed only in the epilogue ->
// DRAM latency hidden under the ~12k-cycle FMA mainloop.
// ---------------------------------------------------------------------------
#define R_    32
#define SWP   130
#define SWP2  65

__global__ void __launch_bounds__(256, 1)
scan_kernel(const float* __restrict__ h0, const float* __restrict__ y0,
            const float* __restrict__ W_ih, const float* __restrict__ W_hh,
            const float* __restrict__ b_hh, const float* __restrict__ Wo,
            const float* __restrict__ bo, float* __restrict__ out)
{
    extern __shared__ float smem[];
    float* sW   = smem;                 // 384*130 = 49920
    float* sH   = sW + G_ * SWP;        // 32*130  = 4160
    float* sWy  = sH + R_ * SWP;        // 384
    float* sBhh = sWy + G_;             // 384
    float* sWo  = sBhh + G_;            // 128
    float* sY   = sWo + H_;             // 32
    float* sRed = sY + R_;              // 8*32

    const int tid  = threadIdx.x;
    const int wid  = tid >> 5;
    const int lane = tid & 31;
    const int b0   = blockIdx.x * R_;

    for (int i = tid; i < G_ * H_; i += 256)
        sW[(i >> 7) * SWP + (i & 127)] = W_hh[i];
    for (int i = tid; i < R_ * H_; i += 256)
        sH[(i >> 7) * SWP + (i & 127)] = h0[(size_t)b0 * H_ + i];
    for (int i = tid; i < G_; i += 256) {
        sWy[i]  = W_ih[(size_t)i * (D_ + 1) + D_];   // y-feedback column
        sBhh[i] = b_hh[i];
    }
    for (int i = tid; i < H_; i += 256) sWo[i] = Wo[i];
    if (tid < R_) sY[tid] = y0[b0 + tid];
    const float bo_v = bo[0];
    __syncthreads();

    const int jgl = lane & 3;
    const int rg  = lane >> 2;
    const int g0  = (wid * 4 + jgl) * 4;   // h-channel base, 0..124

    const ull* sW2 = reinterpret_cast<const ull*>(sW);
    const ull* sH2 = reinterpret_cast<const ull*>(sH);

    for (int t = 0; t < T_; t++) {
        const float* gx = g_gx + ((size_t)t * B_ + b0) * G_;

        // Issue gx loads NOW; first use is ~12k cycles away in the epilogue.
        float4 xr[4], xz[4], xn[4];
        #pragma unroll
        for (int rr = 0; rr < 4; rr++) {
            const float* gxr = gx + (rg + rr * 8) * G_;
            xr[rr] = *reinterpret_cast<const float4*>(&gxr[g0]);
            xz[rr] = *reinterpret_cast<const float4*>(&gxr[H_ + g0]);
            xn[rr] = *reinterpret_cast<const float4*>(&gxr[2 * H_ + g0]);
        }

        ull ar[4][4], az[4][4], an[4][4];
        #pragma unroll
        for (int rr = 0; rr < 4; rr++)
            #pragma unroll
            for (int jj = 0; jj < 4; jj++) {
                ar[rr][jj] = 0ull; az[rr][jj] = 0ull; an[rr][jj] = 0ull;
            }

        // gh = h @ W_hh^T  (FFMA2-issue-bound mainloop)
        #pragma unroll 8
        for (int k2 = 0; k2 < 64; k2++) {
            ull h2[4];
            #pragma unroll
            for (int rr = 0; rr < 4; rr++)
                h2[rr] = sH2[(rg + rr * 8) * SWP2 + k2];
            #pragma unroll
            for (int jj = 0; jj < 4; jj++) {
                int g = g0 + jj;
                ull wr = sW2[g * SWP2 + k2];
                ull wz = sW2[(H_ + g) * SWP2 + k2];
                ull wn = sW2[(2 * H_ + g) * SWP2 + k2];
                #pragma unroll
                for (int rr = 0; rr < 4; rr++) {
                    ar[rr][jj] = ffma2(h2[rr], wr, ar[rr][jj]);
                    az[rr][jj] = ffma2(h2[rr], wz, az[rr][jj]);
                    an[rr][jj] = ffma2(h2[rr], wn, an[rr][jj]);
                }
            }
        }

        // epilogue constants from smem (regs stay for gx + accumulators)
        const float4 wy_r = *reinterpret_cast<const float4*>(&sWy[g0]);
        const float4 wy_z = *reinterpret_cast<const float4*>(&sWy[H_ + g0]);
        const float4 wy_n = *reinterpret_cast<const float4*>(&sWy[2 * H_ + g0]);
        const float4 bh_r = *reinterpret_cast<const float4*>(&sBhh[g0]);
        const float4 bh_z = *reinterpret_cast<const float4*>(&sBhh[H_ + g0]);
        const float4 bh_n = *reinterpret_cast<const float4*>(&sBhh[2 * H_ + g0]);
        const float4 wo4  = *reinterpret_cast<const float4*>(&sWo[g0]);

        // gates + h update + partial y
        float hnew[4][4];
        float pacc[4];
        #pragma unroll
        for (int rr = 0; rr < 4; rr++) {
            int row = rg + rr * 8;
            float y = sY[row];
            float p = 0.f;
            #pragma unroll
            for (int jj = 0; jj < 4; jj++) {
                float gxr_v = (jj == 0) ? xr[rr].x : (jj == 1) ? xr[rr].y : (jj == 2) ? xr[rr].z : xr[rr].w;
                float gxz_v = (jj == 0) ? xz[rr].x : (jj == 1) ? xz[rr].y : (jj == 2) ? xz[rr].z : xz[rr].w;
                float gxn_v = (jj == 0) ? xn[rr].x : (jj == 1) ? xn[rr].y : (jj == 2) ? xn[rr].z : xn[rr].w;
                float wyr_v = (jj == 0) ? wy_r.x : (jj == 1) ? wy_r.y : (jj == 2) ? wy_r.z : wy_r.w;
                float wyz_v = (jj == 0) ? wy_z.x : (jj == 1) ? wy_z.y : (jj == 2) ? wy_z.z : wy_z.w;
                float wyn_v = (jj == 0) ? wy_n.x : (jj == 1) ? wy_n.y : (jj == 2) ? wy_n.z : wy_n.w;
                float bhr_v = (jj == 0) ? bh_r.x : (jj == 1) ? bh_r.y : (jj == 2) ? bh_r.z : bh_r.w;
                float bhz_v = (jj == 0) ? bh_z.x : (jj == 1) ? bh_z.y : (jj == 2) ? bh_z.z : bh_z.w;
                float bhn_v = (jj == 0) ? bh_n.x : (jj == 1) ? bh_n.y : (jj == 2) ? bh_n.z : bh_n.w;

                float r = fast_sigmoid(gxr_v + y * wyr_v + bhr_v + f2sum(ar[rr][jj]));
                float z = fast_sigmoid(gxz_v + y * wyz_v + bhz_v + f2sum(az[rr][jj]));
                float n = fast_tanh  (gxn_v + y * wyn_v + r * (bhn_v + f2sum(an[rr][jj])));
                float hp = sH[row * SWP + g0 + jj];
                float h = (1.f - z) * n + z * hp;
                hnew[rr][jj] = h;
                float w = (jj == 0) ? wo4.x : (jj == 1) ? wo4.y : (jj == 2) ? wo4.z : wo4.w;
                p += h * w;
            }
            pacc[rr] = p;
        }
        __syncthreads();   // all reads of sH for this step are done

        #pragma unroll
        for (int rr = 0; rr < 4; rr++) {
            int row = rg + rr * 8;
            *reinterpret_cast<float2*>(&sH[row * SWP + g0]) =
                make_float2(hnew[rr][0], hnew[rr][1]);
            *reinterpret_cast<float2*>(&sH[row * SWP + g0 + 2]) =
                make_float2(hnew[rr][2], hnew[rr][3]);
        }
        // y reduction: fold 4 jg lanes via shfl, then 8 warps via smem
        #pragma unroll
        for (int rr = 0; rr < 4; rr++) {
            pacc[rr] += __shfl_xor_sync(0xffffffffu, pacc[rr], 1);
            pacc[rr] += __shfl_xor_sync(0xffffffffu, pacc[rr], 2);
        }
        if (jgl == 0) {
            #pragma unroll
            for (int rr = 0; rr < 4; rr++)
                sRed[wid * R_ + rg + rr * 8] = pacc[rr];
        }
        __syncthreads();
        if (tid < R_) {
            float s = bo_v;
            #pragma unroll
            for (int w = 0; w < 8; w++) s += sRed[w * R_ + tid];
            sY[tid] = s;
            out[(size_t)(b0 + tid) * T_ + t] = s;
        }
        __syncthreads();
    }
}

// ---------------------------------------------------------------------------
extern "C" void kernel_launch(void* const* d_in, const int* in_sizes, int n_in,
                              void* d_out, int out_size)
{
    const float* feats = (const float*)d_in[0];
    const float* h0    = (const float*)d_in[1];
    const float* y0    = (const float*)d_in[2];
    const float* W_ih  = (const float*)d_in[3];
    const float* W_hh  = (const float*)d_in[4];
    const float* b_ih  = (const float*)d_in[5];
    const float* b_hh  = (const float*)d_in[6];
    const float* Wo    = (const float*)d_in[7];
    const float* bo    = (const float*)d_in[8];
    float* out = (float*)d_out;

    const int smemA = (A_NT * A_PAD + 2 * A_MT * A_PAD + A_NT) * (int)sizeof(float);
    cudaFuncSetAttribute(gx_kernel, cudaFuncAttributeMaxDynamicSharedMemorySize, smemA);
    gx_kernel<<<148, 256, smemA>>>(feats, W_ih, b_ih);

    const int smemB = (G_ * SWP + R_ * SWP + G_ + G_ + H_ + R_ + 8 * R_) * (int)sizeof(float);
    cudaFuncSetAttribute(scan_kernel, cudaFuncAttributeMaxDynamicSharedMemorySize, smemB);
    scan_kernel<<<B_ / R_, 256, smemB>>>(h0, y0, W_ih, W_hh, b_hh, Wo, bo, out);
}